// round 16
// baseline (speedup 1.0000x reference)
#include <cuda_runtime.h>
#include <cuda_fp16.h>
#include <cstdint>

#define N_NODES 100000
#define N_EDGES 1600000
#define NCOL 64      // 10 one-hot + 54 mlp (one-hot folded into B table)
#define HID 128
#define NGRID 31     // artificial width-capping breakpoints at k*(10/32)
#define NCAND (HID + 9 + NGRID)   // 168: roots + integer boundaries + grid
#define MAXB 176     // padded breakpoint array size
#define MAXSEG 177
#define LUTN 1024
#define NCB 45       // coeff blocks: ceil(MAXSEG/4)

// -------- device-global scratch (allowed; no runtime allocation) --------
__device__ float g_bnd[MAXB + 1];       // sorted breakpoints, +INF padded
__device__ int   g_is64;                // edge_index stored as int64?
__device__ unsigned char g_lut[LUTN];   // dist-cell -> lower bound on segment id
// A stored fp16, PERMUTED row: byte offset 16c holds chunk c's 4 halves then
// chunk (c+8)'s 4 halves -> one LDG.128 per thread fetches all its A values.
__device__ __align__(128) __half g_Ah[MAXSEG * NCOL];
__device__ __align__(128) float  g_B[MAXSEG * NCOL];  // fp32 offset, midpoint-compensated
__device__ __align__(128) float  g_d[(size_t)N_NODES * NCOL];  // sums -> reciprocals

// -------- fused prep: blocks 0..NCB-1 = breakpoints+coeffs, rest zero g_d ----
__global__ void __launch_bounds__(256) k_prep(
        const int* __restrict__ eip,
        const float* __restrict__ W1, const float* __restrict__ b1,
        const float* __restrict__ W2, const float* __restrict__ b2) {
    if (blockIdx.x >= NCB) {
        const float4 z4 = make_float4(0.f, 0.f, 0.f, 0.f);
        unsigned zb  = blockIdx.x - NCB;
        unsigned nzb = gridDim.x - NCB;
        for (unsigned i = zb * 256u + threadIdx.x; i < (unsigned)(N_NODES * 16);
             i += nzb * 256u)
            ((float4*)g_d)[i] = z4;
        return;
    }

    __shared__ float t[NCAND];
    __shared__ int   vld[NCAND];
    __shared__ float sorted[MAXB + 1];
    __shared__ int   s_nb;
    __shared__ float sW1[HID], sb1[HID], sb2[54];
    __shared__ float sW2[HID * 54];
    int tx = threadIdx.x;

    for (int i = tx; i < HID * 54; i += 256) sW2[i] = W2[i];
    if (tx < HID) { sW1[tx] = W1[tx]; sb1[tx] = b1[tx]; }
    if (tx < 54)  sb2[tx] = b2[tx];

    // Candidates:
    //   [0,128)    ReLU roots -b1/W1 (cut where active set changes; continuous)
    //   [128,137)  integer bucket boundaries n=1..9 stored as nextafter(n,0):
    //              strict test (bnd < dist) then equals (dist >= n) exactly,
    //              matching reference floor(dist) INCLUDING dist == n.
    //   [137,168)  uniform grid k*(10/32), k=1..31: artificial width caps so
    //              fp16-slope error (grows with segment width) stays ~<1e-4.
    //              Semantically free: function identical on both sides.
    int j = tx;
    if (j < HID) {
        float w = W1[j], b = b1[j];
        float tj = -b / w;
        t[j]   = tj;
        vld[j] = (w != 0.f) && (tj > 0.f) && (tj < 10.f);  // NaN excluded
        if (j < 9) {
            float n = (float)(j + 1);
            t[HID + j] = __uint_as_float(__float_as_uint(n) - 1u); // nextafter(n,0)
            vld[HID + j] = 1;
        }
        if (j < NGRID) {
            t[HID + 9 + j] = (float)(j + 1) * (10.0f / 32.0f);
            vld[HID + 9 + j] = 1;
        }
    }
    for (int i = tx; i < MAXB + 1; i += 256)
        sorted[i] = __int_as_float(0x7f800000);           // +INF padding
    if (blockIdx.x == 0 && tx < 32) {
        // int64 little-endian values < 2^31 -> all odd 32-bit words are 0.
        unsigned m = __ballot_sync(0xffffffffu, eip[2 * tx + 1] != 0);
        if (tx == 0) g_is64 = (m == 0) ? 1 : 0;
    }
    __syncthreads();

    if (j < HID) {
        // thread j owns candidates: j, 128+j (j<9), 137+j (j<NGRID)
        int c0 = j, c1 = HID + j, c2 = HID + 9 + j;
        float t0 = t[c0];
        float t1 = (j < 9) ? t[c1] : 0.f;
        float t2 = (j < NGRID) ? t[c2] : 0.f;
        int r0 = 0, r1 = 0, r2 = 0, nb = 0;
        for (int i = 0; i < NCAND; i++) {
            if (vld[i]) {
                nb++;
                float ti = t[i];
                if (ti < t0 || (ti == t0 && i < c0)) r0++;
                if (j < 9     && (ti < t1 || (ti == t1 && i < c1))) r1++;
                if (j < NGRID && (ti < t2 || (ti == t2 && i < c2))) r2++;
            }
        }
        __syncwarp();
        if (vld[c0])   sorted[r0] = t0;
        if (j < 9)     sorted[r1] = t1;    // ints always valid
        if (j < NGRID) sorted[r2] = t2;    // grid always valid
        if (j == 0) s_nb = nb;
    }
    __syncthreads();
    int nb = s_nb;

    if (blockIdx.x == 0) {
        for (int i = tx; i < MAXB + 1; i += 256) g_bnd[i] = sorted[i];
        // LUT: deflated threshold -> only UNDERestimates (advance loop fixes it)
        for (int cell = tx; cell < LUTN; cell += 256) {
            float thresh = (float)cell * (10.0f / LUTN) * 0.999999f - 1e-6f;
            int cnt = 0;
            for (int i = 0; i < MAXB; i++)
                cnt += (sorted[i] < thresh) ? 1 : 0;
            g_lut[cell] = (unsigned char)cnt;
        }
    }

    // per-segment affine coefficients: w[k] = relu(A*dist + B)
    int seg = blockIdx.x * 4 + (tx >> 6);   // 0..MAXSEG-1 (+pad)
    int col = tx & 63;                      // 0..63
    if (seg >= MAXSEG) return;
    float A = 0.f, B = 0.f, x = 0.f;
    if (seg <= nb) {
        float lo = (seg == 0) ? 0.f  : sorted[seg - 1];
        float hi = (seg == nb) ? 10.f : sorted[seg];
        x = 0.5f * (lo + hi);   // interior midpoint -> exact active set / bucket
        if (col < 10) {
            int bkt = (int)(lo + 1e-6f);          // lo is nextafter-adjusted
            if (bkt > 9) bkt = 9;
            if (bkt < 0) bkt = 0;
            B = (bkt == col) ? 1.f : 0.f;         // one-hot baked in
        } else {
            int m = col - 10;        // 0..53
            B = sb2[m];
            #pragma unroll 8
            for (int jj = 0; jj < HID; jj++) {
                float w1 = sW1[jj], bb = sb1[jj];
                if (fmaf(w1, x, bb) > 0.f) {
                    float w2 = sW2[jj * 54 + m];
                    A = fmaf(w1, w2, A);
                    B = fmaf(bb, w2, B);
                }
            }
        }
    }
    // fp16 slope + exact midpoint compensation in fp32 B:
    // w'(x_mid) == w(x_mid); elsewhere |err| <= |A - aq| * halfwidth (<~1e-4)
    __half ah = __float2half_rn(A);
    float  aq = __half2float(ah);
    int cc = col >> 2, r = col & 3;
    int apos = (cc < 8) ? (cc * 8 + r) : ((cc - 8) * 8 + 4 + r);  // permuted slot
    g_Ah[seg * NCOL + apos] = ah;
    g_B [seg * NCOL + col]  = fmaf(A - aq, x, B);
}

// -------- invert accumulator: d -> (d==0 ? 0 : 1/d) --------
__global__ void k_invert() {
    unsigned i = blockIdx.x * blockDim.x + threadIdx.x;
    if (i < (unsigned)(N_NODES * (NCOL / 4))) {
        float4 v = ((float4*)g_d)[i];
        v.x = (v.x != 0.f) ? 1.f / v.x : 0.f;
        v.y = (v.y != 0.f) ? 1.f / v.y : 0.f;
        v.z = (v.z != 0.f) ? 1.f / v.z : 0.f;
        v.w = (v.w != 0.f) ? 1.f / v.w : 0.f;
        ((float4*)g_d)[i] = v;
    }
}

// -------- main: SCATTER (atomic segment-sum) / GATHER (normalize + write) --------
// 8 threads per edge, 2 float4 chunks per thread (c and c+8).
// Tables read via __ldg: L1-resident, broadcast across each edge's 8 threads.
template <bool SCATTER>
__global__ void __launch_bounds__(256)
k_main(const float* __restrict__ edge_attr, const int* __restrict__ eip,
       float4* __restrict__ out) {
    __shared__ float sbnd[MAXB + 1];
    __shared__ unsigned char slut[LUTN];
    for (int i = threadIdx.x; i < MAXB + 1; i += 256) sbnd[i] = g_bnd[i];
    for (int i = threadIdx.x; i < LUTN; i += 256) slut[i] = g_lut[i];
    __syncthreads();

    const int sh = g_is64;               // shift: int64 -> stride-2 words
    const unsigned total  = (unsigned)N_EDGES * 8u;
    const unsigned stride = gridDim.x * 256u;
    for (unsigned idx = blockIdx.x * 256u + threadIdx.x; idx < total; idx += stride) {
        int e = (int)(idx >> 3);
        int c = (int)(idx & 7u);
        float dist = __ldg(edge_attr + e);
        int src = __ldg(eip + (e << sh));

        // segment id = #(bnd < dist): LUT lower bound + exact advance
        int cell = (int)(dist * (LUTN / 10.0f));
        cell = (cell < 0) ? 0 : ((cell > LUTN - 1) ? LUTN - 1 : cell);
        int pos = slut[cell];
        while (sbnd[pos] < dist) pos++;          // bnd padded +INF

        // ONE 16B load gets all 8 fp16 slopes (chunk c + chunk c+8, permuted row)
        const uint4 av = __ldg((const uint4*)g_Ah + pos * 8 + c);
        const __half2* hp = (const __half2*)&av;
        const float2 a01 = __half22float2(hp[0]);
        const float2 a23 = __half22float2(hp[1]);
        const float2 a45 = __half22float2(hp[2]);
        const float2 a67 = __half22float2(hp[3]);

        const float4* pb = (const float4*)g_B + pos * 16 + c;
        const float4 b0 = __ldg(pb), b1 = __ldg(pb + 8);
        float4 w0, w1;
        w0.x = fmaxf(fmaf(a01.x, dist, b0.x), 0.f);
        w0.y = fmaxf(fmaf(a01.y, dist, b0.y), 0.f);
        w0.z = fmaxf(fmaf(a23.x, dist, b0.z), 0.f);
        w0.w = fmaxf(fmaf(a23.y, dist, b0.w), 0.f);
        w1.x = fmaxf(fmaf(a45.x, dist, b1.x), 0.f);
        w1.y = fmaxf(fmaf(a45.y, dist, b1.y), 0.f);
        w1.z = fmaxf(fmaf(a67.x, dist, b1.z), 0.f);
        w1.w = fmaxf(fmaf(a67.y, dist, b1.w), 0.f);

        if (SCATTER) {
            float* dst = g_d + src * NCOL + c * 4;
            // skip all-zero chunks (one-hot chunks + dead ReLU runs)
            if ((w0.x != 0.f) | (w0.y != 0.f) | (w0.z != 0.f) | (w0.w != 0.f))
                asm volatile("red.global.add.v4.f32 [%0], {%1,%2,%3,%4};"
                             :: "l"(dst), "f"(w0.x), "f"(w0.y), "f"(w0.z), "f"(w0.w)
                             : "memory");
            if ((w1.x != 0.f) | (w1.y != 0.f) | (w1.z != 0.f) | (w1.w != 0.f))
                asm volatile("red.global.add.v4.f32 [%0], {%1,%2,%3,%4};"
                             :: "l"(dst + 32), "f"(w1.x), "f"(w1.y), "f"(w1.z), "f"(w1.w)
                             : "memory");
        } else {
            const float4* pd = (const float4*)g_d + src * 16 + c;
            const float4 d0 = __ldg(pd), d1 = __ldg(pd + 8);
            float4 o0 = make_float4(w0.x * d0.x, w0.y * d0.y, w0.z * d0.z, w0.w * d0.w);
            float4 o1 = make_float4(w1.x * d1.x, w1.y * d1.y, w1.z * d1.z, w1.w * d1.w);
            __stcs(out + e * 16 + c, o0);        // streaming: don't evict d from L2
            __stcs(out + e * 16 + c + 8, o1);
        }
    }
}

extern "C" void kernel_launch(void* const* d_in, const int* in_sizes, int n_in,
                              void* d_out, int out_size) {
    // metadata order: x, edge_index, edge_attr, W1, b1, W2, b2
    const int*   eip       = (const int*)d_in[1];
    const float* edge_attr = (const float*)d_in[2];
    const float* W1        = (const float*)d_in[3];
    const float* b1        = (const float*)d_in[4];
    const float* W2        = (const float*)d_in[5];
    const float* b2        = (const float*)d_in[6];
    (void)in_sizes; (void)n_in; (void)out_size;

    const int nq4 = N_NODES * (NCOL / 4);      // 1.6M float4s in d

    k_prep<<<1184, 256>>>(eip, W1, b1, W2, b2);
    k_main<true><<<1184, 256>>>(edge_attr, eip, nullptr);
    k_invert<<<(nq4 + 255) / 256, 256>>>();
    k_main<false><<<1184, 256>>>(edge_attr, eip, (float4*)d_out);
}

// round 17
// speedup vs baseline: 1.5487x; 1.5487x over previous
#include <cuda_runtime.h>
#include <cuda_fp16.h>
#include <cstdint>

#define N_NODES 100000
#define N_EDGES 1600000
#define NCOL 64      // 10 one-hot + 54 mlp (one-hot folded into B table)
#define HID 128
#define NGRID 31     // artificial width-capping breakpoints at k*(10/32)
#define NCAND (HID + 9 + NGRID)   // 168: roots + integer boundaries + grid
#define MAXB 176     // padded breakpoint array size
#define MAXSEG 177
#define LUTN 1024
#define NCB 45       // coeff blocks: ceil(MAXSEG/4)

// -------- device-global scratch (allowed; no runtime allocation) --------
__device__ float g_bnd[MAXB + 1];       // sorted breakpoints, +INF padded
__device__ int   g_is64;                // edge_index stored as int64?
__device__ unsigned char g_lut[LUTN];   // dist-cell -> lower bound on segment id
// A stored fp16, PERMUTED row: byte offset 16c holds chunk c's 4 halves then
// chunk (c+8)'s 4 halves -> one LDG.128 per thread fetches all its A values.
__device__ __align__(128) __half g_Ah[MAXSEG * NCOL];
__device__ __align__(128) float  g_B[MAXSEG * NCOL];  // fp32 offset, midpoint-compensated
__device__ __align__(128) float  g_d[(size_t)N_NODES * NCOL];  // sums -> reciprocals

// -------- fused prep: blocks 0..NCB-1 = breakpoints+coeffs, rest zero g_d ----
__global__ void __launch_bounds__(256) k_prep(
        const int* __restrict__ eip,
        const float* __restrict__ W1, const float* __restrict__ b1,
        const float* __restrict__ W2, const float* __restrict__ b2) {
    if (blockIdx.x >= NCB) {
        const float4 z4 = make_float4(0.f, 0.f, 0.f, 0.f);
        unsigned zb  = blockIdx.x - NCB;
        unsigned nzb = gridDim.x - NCB;
        for (unsigned i = zb * 256u + threadIdx.x; i < (unsigned)(N_NODES * 16);
             i += nzb * 256u)
            ((float4*)g_d)[i] = z4;
        return;
    }

    __shared__ float t[NCAND];
    __shared__ int   vld[NCAND];
    __shared__ float sorted[MAXB + 1];
    __shared__ int   s_nb;
    __shared__ float sW1[HID], sb1[HID], sb2[54];
    __shared__ float sW2[HID * 54];
    int tx = threadIdx.x;

    for (int i = tx; i < HID * 54; i += 256) sW2[i] = W2[i];
    if (tx < HID) { sW1[tx] = W1[tx]; sb1[tx] = b1[tx]; }
    if (tx < 54)  sb2[tx] = b2[tx];

    // Candidates:
    //   [0,128)    ReLU roots -b1/W1 (cut where active set changes; continuous)
    //   [128,137)  integer bucket boundaries n=1..9 stored as nextafter(n,0):
    //              strict test (bnd < dist) then equals (dist >= n) exactly,
    //              matching reference floor(dist) INCLUDING dist == n.
    //   [137,168)  uniform grid k*(10/32), k=1..31: artificial width caps so
    //              fp16-slope error (grows with segment width) stays <~1e-4.
    //              Semantically free: function identical on both sides.
    int j = tx;
    if (j < HID) {
        float w = W1[j], b = b1[j];
        float tj = -b / w;
        t[j]   = tj;
        vld[j] = (w != 0.f) && (tj > 0.f) && (tj < 10.f);  // NaN excluded
        if (j < 9) {
            float n = (float)(j + 1);
            t[HID + j] = __uint_as_float(__float_as_uint(n) - 1u); // nextafter(n,0)
            vld[HID + j] = 1;
        }
        if (j < NGRID) {
            t[HID + 9 + j] = (float)(j + 1) * (10.0f / 32.0f);
            vld[HID + 9 + j] = 1;
        }
    }
    for (int i = tx; i < MAXB + 1; i += 256)
        sorted[i] = __int_as_float(0x7f800000);           // +INF padding
    if (blockIdx.x == 0 && tx < 32) {
        // int64 little-endian values < 2^31 -> all odd 32-bit words are 0.
        unsigned m = __ballot_sync(0xffffffffu, eip[2 * tx + 1] != 0);
        if (tx == 0) g_is64 = (m == 0) ? 1 : 0;
    }
    __syncthreads();

    if (j < HID) {
        // thread j owns candidates: j, 128+j (j<9), 137+j (j<NGRID)
        int c0 = j, c1 = HID + j, c2 = HID + 9 + j;
        float t0 = t[c0];
        float t1 = (j < 9) ? t[c1] : 0.f;
        float t2 = (j < NGRID) ? t[c2] : 0.f;
        int r0 = 0, r1 = 0, r2 = 0, nb = 0;
        for (int i = 0; i < NCAND; i++) {
            if (vld[i]) {
                nb++;
                float ti = t[i];
                if (ti < t0 || (ti == t0 && i < c0)) r0++;
                if (j < 9     && (ti < t1 || (ti == t1 && i < c1))) r1++;
                if (j < NGRID && (ti < t2 || (ti == t2 && i < c2))) r2++;
            }
        }
        __syncwarp();
        if (vld[c0])   sorted[r0] = t0;
        if (j < 9)     sorted[r1] = t1;    // ints always valid
        if (j < NGRID) sorted[r2] = t2;    // grid always valid
        if (j == 0) s_nb = nb;
    }
    __syncthreads();
    int nb = s_nb;

    if (blockIdx.x == 0) {
        for (int i = tx; i < MAXB + 1; i += 256) g_bnd[i] = sorted[i];
        // LUT: deflated threshold -> only UNDERestimates (advance loop fixes it)
        for (int cell = tx; cell < LUTN; cell += 256) {
            float thresh = (float)cell * (10.0f / LUTN) * 0.999999f - 1e-6f;
            int cnt = 0;
            for (int i = 0; i < MAXB; i++)
                cnt += (sorted[i] < thresh) ? 1 : 0;
            g_lut[cell] = (unsigned char)cnt;
        }
    }

    // per-segment affine coefficients: w[k] = relu(A*dist + B)
    int seg = blockIdx.x * 4 + (tx >> 6);   // 0..MAXSEG-1 (+pad)
    int col = tx & 63;                      // 0..63
    if (seg >= MAXSEG) return;
    float A = 0.f, B = 0.f, x = 0.f;
    if (seg <= nb) {
        float lo = (seg == 0) ? 0.f  : sorted[seg - 1];
        float hi = (seg == nb) ? 10.f : sorted[seg];
        x = 0.5f * (lo + hi);   // interior midpoint -> exact active set / bucket
        if (col < 10) {
            int bkt = (int)(lo + 1e-6f);          // lo is nextafter-adjusted
            if (bkt > 9) bkt = 9;
            if (bkt < 0) bkt = 0;
            B = (bkt == col) ? 1.f : 0.f;         // one-hot baked in
        } else {
            int m = col - 10;        // 0..53
            B = sb2[m];
            #pragma unroll 8
            for (int jj = 0; jj < HID; jj++) {
                float w1 = sW1[jj], bb = sb1[jj];
                if (fmaf(w1, x, bb) > 0.f) {
                    float w2 = sW2[jj * 54 + m];
                    A = fmaf(w1, w2, A);
                    B = fmaf(bb, w2, B);
                }
            }
        }
    }
    // fp16 slope + exact midpoint compensation in fp32 B:
    // w'(x_mid) == w(x_mid); elsewhere |err| <= |A - aq| * halfwidth (<~1e-4)
    __half ah = __float2half_rn(A);
    float  aq = __half2float(ah);
    int cc = col >> 2, r = col & 3;
    int apos = (cc < 8) ? (cc * 8 + r) : ((cc - 8) * 8 + 4 + r);  // permuted slot
    g_Ah[seg * NCOL + apos] = ah;
    g_B [seg * NCOL + col]  = fmaf(A - aq, x, B);
}

// -------- invert accumulator: d -> (d==0 ? 0 : 1/d) --------
__global__ void k_invert() {
    unsigned i = blockIdx.x * blockDim.x + threadIdx.x;
    if (i < (unsigned)(N_NODES * (NCOL / 4))) {
        float4 v = ((float4*)g_d)[i];
        v.x = (v.x != 0.f) ? 1.f / v.x : 0.f;
        v.y = (v.y != 0.f) ? 1.f / v.y : 0.f;
        v.z = (v.z != 0.f) ? 1.f / v.z : 0.f;
        v.w = (v.w != 0.f) ? 1.f / v.w : 0.f;
        ((float4*)g_d)[i] = v;
    }
}

// -------- main: SCATTER (atomic segment-sum) / GATHER (normalize + write) --------
// 8 threads per edge, 2 float4 chunks per thread (c and c+8).
// Tables read via __ldg: L1-resident, broadcast across each edge's 8 threads.
template <bool SCATTER>
__global__ void __launch_bounds__(256)
k_main(const float* __restrict__ edge_attr, const int* __restrict__ eip,
       float4* __restrict__ out) {
    __shared__ float sbnd[MAXB + 1];
    __shared__ unsigned char slut[LUTN];
    for (int i = threadIdx.x; i < MAXB + 1; i += 256) sbnd[i] = g_bnd[i];
    for (int i = threadIdx.x; i < LUTN; i += 256) slut[i] = g_lut[i];
    __syncthreads();

    const int sh = g_is64;               // shift: int64 -> stride-2 words
    const unsigned total  = (unsigned)N_EDGES * 8u;
    const unsigned stride = gridDim.x * 256u;
    for (unsigned idx = blockIdx.x * 256u + threadIdx.x; idx < total; idx += stride) {
        int e = (int)(idx >> 3);
        int c = (int)(idx & 7u);
        float dist = __ldg(edge_attr + e);
        int src = __ldg(eip + (e << sh));

        // segment id = #(bnd < dist): LUT lower bound + exact advance
        int cell = (int)(dist * (LUTN / 10.0f));
        cell = (cell < 0) ? 0 : ((cell > LUTN - 1) ? LUTN - 1 : cell);
        int pos = slut[cell];
        while (sbnd[pos] < dist) pos++;          // bnd padded +INF

        // ONE 16B load gets all 8 fp16 slopes (chunk c + chunk c+8, permuted row)
        const uint4 av = __ldg((const uint4*)g_Ah + pos * 8 + c);
        const __half2* hp = (const __half2*)&av;
        const float2 a01 = __half22float2(hp[0]);
        const float2 a23 = __half22float2(hp[1]);
        const float2 a45 = __half22float2(hp[2]);
        const float2 a67 = __half22float2(hp[3]);

        const float4* pb = (const float4*)g_B + pos * 16 + c;
        const float4 b0 = __ldg(pb), b1 = __ldg(pb + 8);
        float4 w0, w1;
        w0.x = fmaxf(fmaf(a01.x, dist, b0.x), 0.f);
        w0.y = fmaxf(fmaf(a01.y, dist, b0.y), 0.f);
        w0.z = fmaxf(fmaf(a23.x, dist, b0.z), 0.f);
        w0.w = fmaxf(fmaf(a23.y, dist, b0.w), 0.f);
        w1.x = fmaxf(fmaf(a45.x, dist, b1.x), 0.f);
        w1.y = fmaxf(fmaf(a45.y, dist, b1.y), 0.f);
        w1.z = fmaxf(fmaf(a67.x, dist, b1.z), 0.f);
        w1.w = fmaxf(fmaf(a67.y, dist, b1.w), 0.f);

        if (SCATTER) {
            float* dst = g_d + src * NCOL + c * 4;
            // skip all-zero chunks (one-hot chunks + dead ReLU runs)
            if ((w0.x != 0.f) | (w0.y != 0.f) | (w0.z != 0.f) | (w0.w != 0.f))
                asm volatile("red.global.add.v4.f32 [%0], {%1,%2,%3,%4};"
                             :: "l"(dst), "f"(w0.x), "f"(w0.y), "f"(w0.z), "f"(w0.w)
                             : "memory");
            if ((w1.x != 0.f) | (w1.y != 0.f) | (w1.z != 0.f) | (w1.w != 0.f))
                asm volatile("red.global.add.v4.f32 [%0], {%1,%2,%3,%4};"
                             :: "l"(dst + 32), "f"(w1.x), "f"(w1.y), "f"(w1.z), "f"(w1.w)
                             : "memory");
        } else {
            const float4* pd = (const float4*)g_d + src * 16 + c;
            const float4 d0 = __ldg(pd), d1 = __ldg(pd + 8);
            float4 o0 = make_float4(w0.x * d0.x, w0.y * d0.y, w0.z * d0.z, w0.w * d0.w);
            float4 o1 = make_float4(w1.x * d1.x, w1.y * d1.y, w1.z * d1.z, w1.w * d1.w);
            float4* po = out + e * 16 + c;
            __stcs(po, o0);                      // streaming: don't evict d from L2
            __stcs(po + 8, o1);
        }
    }
}

extern "C" void kernel_launch(void* const* d_in, const int* in_sizes, int n_in,
                              void* d_out, int out_size) {
    // metadata order: x, edge_index, edge_attr, W1, b1, W2, b2
    const int*   eip       = (const int*)d_in[1];
    const float* edge_attr = (const float*)d_in[2];
    const float* W1        = (const float*)d_in[3];
    const float* b1        = (const float*)d_in[4];
    const float* W2        = (const float*)d_in[5];
    const float* b2        = (const float*)d_in[6];
    (void)in_sizes; (void)n_in; (void)out_size;

    const int nq4 = N_NODES * (NCOL / 4);      // 1.6M float4s in d

    k_prep<<<1184, 256>>>(eip, W1, b1, W2, b2);
    k_main<true><<<1184, 256>>>(edge_attr, eip, nullptr);
    k_invert<<<(nq4 + 255) / 256, 256>>>();
    k_main<false><<<1184, 256>>>(edge_attr, eip, (float4*)d_out);
}